// round 2
// baseline (speedup 1.0000x reference)
#include <cuda_runtime.h>
#include <math.h>

// ---------------------------------------------------------------------------
// Problem constants
// ---------------------------------------------------------------------------
#define BATCH   4096
#define NTOK    64          // window size 8x8
#define CDIM    96
#define NHEADS  3
#define HD      32          // head dim
#define K4      384         // 4*C
#define SCALE   0.17677669529663687f   // 32^-0.5

// ---------------------------------------------------------------------------
// Scratch (device globals: the sanctioned alloc-free workaround)
// ---------------------------------------------------------------------------
__device__ float g_Ys [(size_t)BATCH * NTOK * K4];    // state projections
__device__ float g_Ye [(size_t)BATCH * NTOK * K4];    // input projections
__device__ float g_Mcv[(size_t)BATCH * NTOK * CDIM];
__device__ float g_Msv[(size_t)BATCH * NTOK * CDIM];
__device__ float g_Mch[(size_t)BATCH * NTOK * CDIM];
__device__ float g_Msh[(size_t)BATCH * NTOK * CDIM];

// ---------------------------------------------------------------------------
// Generic GEMM: C[M,Nn] = concat(A1,A2)[M,K] @ W[Nn,K]^T + bias[Nn]
// Tile 64x64, k-chunk 32, 256 threads, 4x4 register blocking.
// M must be a multiple of 64 (262144 here). Nn handled with bounds checks.
// K must be a multiple of 32, Ksplit a multiple of 32.
// ---------------------------------------------------------------------------
#define BM 64
#define BN 64
#define BKC 32
#define APAD 68   // 64 + 4: keeps float4 compute loads aligned & conflict-free

__global__ __launch_bounds__(256)
void gemm_bias(const float* __restrict__ A1, const float* __restrict__ A2,
               int lda1, int lda2, int Ksplit, int K, int Nn,
               const float* __restrict__ W, const float* __restrict__ bias,
               float* __restrict__ Cout)
{
    __shared__ float As[BKC][APAD];
    __shared__ float Bs[BKC][APAD];

    const int t     = threadIdx.x;
    const int mBase = blockIdx.x * BM;
    const int nBase = blockIdx.y * BN;
    const int kk    = t & 31;     // 0..31 : k within chunk
    const int rrow  = t >> 5;     // 0..7
    const int tx    = t & 15;     // m micro-tile
    const int ty    = t >> 4;     // n micro-tile

    float acc[4][4];
    #pragma unroll
    for (int i = 0; i < 4; i++)
        #pragma unroll
        for (int j = 0; j < 4; j++) acc[i][j] = 0.f;

    for (int k0 = 0; k0 < K; k0 += BKC) {
        const float* A;
        int lda, kcol;
        if (k0 < Ksplit) { A = A1; lda = lda1; kcol = k0; }
        else             { A = A2; lda = lda2; kcol = k0 - Ksplit; }

        #pragma unroll
        for (int r = 0; r < 8; r++) {
            int m = rrow + r * 8;
            As[kk][m] = A[(size_t)(mBase + m) * lda + kcol + kk];
        }
        #pragma unroll
        for (int r = 0; r < 8; r++) {
            int n = rrow + r * 8;
            float v = 0.f;
            if (nBase + n < Nn) v = W[(size_t)(nBase + n) * K + k0 + kk];
            Bs[kk][n] = v;
        }
        __syncthreads();

        #pragma unroll
        for (int q = 0; q < BKC; q++) {
            float4 av = *(const float4*)&As[q][tx * 4];
            float4 bv = *(const float4*)&Bs[q][ty * 4];
            float am[4] = {av.x, av.y, av.z, av.w};
            float bn[4] = {bv.x, bv.y, bv.z, bv.w};
            #pragma unroll
            for (int i = 0; i < 4; i++)
                #pragma unroll
                for (int j = 0; j < 4; j++)
                    acc[i][j] = fmaf(am[i], bn[j], acc[i][j]);
        }
        __syncthreads();
    }

    #pragma unroll
    for (int i = 0; i < 4; i++) {
        int row = mBase + tx * 4 + i;
        #pragma unroll
        for (int j = 0; j < 4; j++) {
            int col = nBase + ty * 4 + j;
            if (col < Nn)
                Cout[(size_t)row * Nn + col] = acc[i][j] + bias[col];
        }
    }
}

// ---------------------------------------------------------------------------
// Window attention. Grid (BATCH, NHEADS, 2). 128 threads.
//   z = 0: source = Ys  -> typeA = attn_cv (scale),  typeB = attn_sh (scale^2)
//   z = 1: source = Ye  -> typeA = attn_sv (1.0),    typeB = attn_ch (scale)
// Tiles j4 = 0(k), 1(v), 2(qA), 3(qB) -- identical role for both z.
// 4 warps: warps {0,1} = type A (query-row halves), {2,3} = type B.
// Dynamic smem: 4 q/k/v tiles [64][33] + scores S[2][64][65] = 67072 B.
// ---------------------------------------------------------------------------
#define TPITCH 33
#define TSIZE  (NTOK * TPITCH)     // 2112 floats per tile
#define SPITCH 65
#define ATTN_SMEM ((4 * TSIZE + 2 * NTOK * SPITCH) * sizeof(float))

__global__ __launch_bounds__(128)
void attn_kernel(const float* __restrict__ tcv, const float* __restrict__ tsv,
                 const float* __restrict__ tch, const float* __restrict__ tsh,
                 const int*   __restrict__ rel_idx)
{
    extern __shared__ float smem[];
    float* tiles = smem;                      // 4 * 2112
    float* S     = smem + 4 * TSIZE;          // 2 * 64 * 65

    const int b = blockIdx.x;
    const int h = blockIdx.y;
    const int z = blockIdx.z;

    const float* Y = z ? g_Ye : g_Ys;
    const float* tblA = z ? tsv : tcv;
    const float* tblB = z ? tch : tsh;
    const float  sclA = z ? 1.0f  : SCALE;
    const float  sclB = z ? SCALE : SCALE * SCALE;
    float* outA = z ? g_Msv : g_Mcv;
    float* outB = z ? g_Mch : g_Msh;

    const int t    = threadIdx.x;
    const int lane = t & 31;
    const int warp = t >> 5;

    // ---- load 4 projection tiles [64][32] (cols j4*96 + h*32 + lane) ----
    #pragma unroll
    for (int j4 = 0; j4 < 4; j4++) {
        #pragma unroll
        for (int r = 0; r < 16; r++) {
            int i = warp * 16 + r;
            tiles[j4 * TSIZE + i * TPITCH + lane] =
                Y[(size_t)(b * NTOK + i) * K4 + j4 * CDIM + h * HD + lane];
        }
    }

    // ---- pre-fill scores with relative-position bias ----
    for (int idx = t; idx < NTOK * NTOK; idx += 128) {
        int r = rel_idx[idx];
        int i = idx >> 6, j = idx & 63;
        float ba = tblA[r * NHEADS + h];
        float bb = tblB[r * NHEADS + h];
        S[i * SPITCH + j]                  = ba;
        S[(NTOK + i) * SPITCH + j]         = bb;
    }
    __syncthreads();

    const int type = warp >> 1;     // 0 = A, 1 = B
    const int half = warp & 1;      // query-row half
    const float* q = tiles + (2 + type) * TSIZE;
    const float* k = tiles;                 // j4 = 0
    const float* v = tiles + TSIZE;         // j4 = 1
    const float  scl = type ? sclB : sclA;
    float* St = S + type * NTOK * SPITCH;
    float* outP = type ? outB : outA;

    // ---- Q @ K^T (lane owns columns j0=lane, j1=lane+32; 4-row blocking) ----
    const int j0 = lane, j1 = lane + 32;
    for (int i0 = half * 32; i0 < half * 32 + 32; i0 += 4) {
        float a0[4], a1[4];
        #pragma unroll
        for (int r = 0; r < 4; r++) { a0[r] = 0.f; a1[r] = 0.f; }
        #pragma unroll
        for (int d = 0; d < HD; d++) {
            float k0v = k[j0 * TPITCH + d];
            float k1v = k[j1 * TPITCH + d];
            #pragma unroll
            for (int r = 0; r < 4; r++) {
                float qv = q[(i0 + r) * TPITCH + d];
                a0[r] = fmaf(qv, k0v, a0[r]);
                a1[r] = fmaf(qv, k1v, a1[r]);
            }
        }
        #pragma unroll
        for (int r = 0; r < 4; r++) {
            St[(i0 + r) * SPITCH + j0] = fmaf(scl, a0[r], St[(i0 + r) * SPITCH + j0]);
            St[(i0 + r) * SPITCH + j1] = fmaf(scl, a1[r], St[(i0 + r) * SPITCH + j1]);
        }
    }
    __syncwarp();

    // ---- row softmax (each lane owns one row of its half) ----
    {
        int row = half * 32 + lane;
        float* Sr = St + row * SPITCH;
        float mx = -1e30f;
        #pragma unroll
        for (int j = 0; j < NTOK; j++) mx = fmaxf(mx, Sr[j]);
        float sum = 0.f;
        #pragma unroll
        for (int j = 0; j < NTOK; j++) {
            float e = __expf(Sr[j] - mx);
            Sr[j] = e;
            sum += e;
        }
        float inv = 1.f / sum;
        #pragma unroll
        for (int j = 0; j < NTOK; j++) Sr[j] *= inv;
    }
    __syncwarp();

    // ---- P @ V (lane owns output dim d=lane; 4-row blocking) ----
    for (int i0 = half * 32; i0 < half * 32 + 32; i0 += 4) {
        float acc[4] = {0.f, 0.f, 0.f, 0.f};
        #pragma unroll 8
        for (int j = 0; j < NTOK; j++) {
            float vv = v[j * TPITCH + lane];
            #pragma unroll
            for (int r = 0; r < 4; r++)
                acc[r] = fmaf(St[(i0 + r) * SPITCH + j], vv, acc[r]);
        }
        #pragma unroll
        for (int r = 0; r < 4; r++)
            outP[(size_t)(b * NTOK + i0 + r) * CDIM + h * HD + lane] = acc[r];
    }
}

// ---------------------------------------------------------------------------
// Launch
// ---------------------------------------------------------------------------
extern "C" void kernel_launch(void* const* d_in, const int* in_sizes, int n_in,
                              void* d_out, int out_size)
{
    const float* input_x = (const float*)d_in[0];
    const float* state_x = (const float*)d_in[1];
    const float* Ws      = (const float*)d_in[2];
    const float* bs      = (const float*)d_in[3];
    const float* We      = (const float*)d_in[4];
    const float* be      = (const float*)d_in[5];
    const float* tcv     = (const float*)d_in[6];
    const float* tsv     = (const float*)d_in[7];
    const float* tch     = (const float*)d_in[8];
    const float* tsh     = (const float*)d_in[9];
    const float* Wpv     = (const float*)d_in[10];
    const float* bpv     = (const float*)d_in[11];
    const float* Wph     = (const float*)d_in[12];
    const float* bph     = (const float*)d_in[13];
    const int*   rel_idx = (const int*)d_in[14];

    float* out   = (float*)d_out;
    float* state = out + (size_t)BATCH * NTOK * CDIM;

    float *pYs, *pYe, *pMcv, *pMsv, *pMch, *pMsh;
    cudaGetSymbolAddress((void**)&pYs,  g_Ys);
    cudaGetSymbolAddress((void**)&pYe,  g_Ye);
    cudaGetSymbolAddress((void**)&pMcv, g_Mcv);
    cudaGetSymbolAddress((void**)&pMsv, g_Msv);
    cudaGetSymbolAddress((void**)&pMch, g_Mch);
    cudaGetSymbolAddress((void**)&pMsh, g_Msh);

    cudaFuncSetAttribute(attn_kernel,
                         cudaFuncAttributeMaxDynamicSharedMemorySize,
                         (int)ATTN_SMEM);

    const int M = BATCH * NTOK;          // 262144

    // Stage 1: projections  Y = X @ W^T + b   -> [M, 384]
    {
        dim3 grid(M / BM, K4 / BN);
        gemm_bias<<<grid, 256>>>(state_x, state_x, CDIM, CDIM, CDIM, CDIM, K4,
                                 Ws, bs, pYs);
        gemm_bias<<<grid, 256>>>(input_x, input_x, CDIM, CDIM, CDIM, CDIM, K4,
                                 We, be, pYe);
    }

    // Stage 2: 4 window attentions per (b, h)
    {
        dim3 grid(BATCH, NHEADS, 2);
        attn_kernel<<<grid, 128, ATTN_SMEM>>>(tcv, tsv, tch, tsh, rel_idx);
    }

    // Stage 3: output projections on concatenated merges
    {
        dim3 grid(M / BM, (CDIM + BN - 1) / BN);   // (4096, 2)
        gemm_bias<<<grid, 256>>>(pMcv, pMsv, CDIM, CDIM, CDIM, 2 * CDIM, CDIM,
                                 Wpv, bpv, out);
        gemm_bias<<<grid, 256>>>(pMch, pMsh, CDIM, CDIM, CDIM, 2 * CDIM, CDIM,
                                 Wph, bph, state);
    }
}

// round 3
// speedup vs baseline: 1.0010x; 1.0010x over previous
#include <cuda_runtime.h>
#include <math.h>

// ---------------------------------------------------------------------------
// Problem constants
// ---------------------------------------------------------------------------
#define BATCH   4096
#define NTOK    64          // window size 8x8
#define CDIM    96
#define NHEADS  3
#define HD      32          // head dim
#define K4      384         // 4*C
#define SCALE   0.17677669529663687f   // 32^-0.5

// ---------------------------------------------------------------------------
// Scratch (device globals: the sanctioned alloc-free workaround)
// ---------------------------------------------------------------------------
__device__ float g_Ys [(size_t)BATCH * NTOK * K4];    // state projections
__device__ float g_Ye [(size_t)BATCH * NTOK * K4];    // input projections
__device__ float g_Mcv[(size_t)BATCH * NTOK * CDIM];
__device__ float g_Msv[(size_t)BATCH * NTOK * CDIM];
__device__ float g_Mch[(size_t)BATCH * NTOK * CDIM];
__device__ float g_Msh[(size_t)BATCH * NTOK * CDIM];

// ---------------------------------------------------------------------------
// Generic GEMM: C[M,Nn] = concat(A1,A2)[M,K] @ W[Nn,K]^T + bias[Nn]
// Tile 64x64, k-chunk 32, 256 threads, 4x4 register blocking.
// M must be a multiple of 64 (262144 here). Nn handled with bounds checks.
// K must be a multiple of 32, Ksplit a multiple of 32.
// ---------------------------------------------------------------------------
#define BM 64
#define BN 64
#define BKC 32
#define APAD 68   // 64 + 4: keeps float4 compute loads aligned & conflict-free

__global__ __launch_bounds__(256)
void gemm_bias(const float* __restrict__ A1, const float* __restrict__ A2,
               int lda1, int lda2, int Ksplit, int K, int Nn,
               const float* __restrict__ W, const float* __restrict__ bias,
               float* __restrict__ Cout)
{
    __shared__ float As[BKC][APAD];
    __shared__ float Bs[BKC][APAD];

    const int t     = threadIdx.x;
    const int mBase = blockIdx.x * BM;
    const int nBase = blockIdx.y * BN;
    const int kk    = t & 31;     // 0..31 : k within chunk
    const int rrow  = t >> 5;     // 0..7
    const int tx    = t & 15;     // m micro-tile
    const int ty    = t >> 4;     // n micro-tile

    float acc[4][4];
    #pragma unroll
    for (int i = 0; i < 4; i++)
        #pragma unroll
        for (int j = 0; j < 4; j++) acc[i][j] = 0.f;

    for (int k0 = 0; k0 < K; k0 += BKC) {
        const float* A;
        int lda, kcol;
        if (k0 < Ksplit) { A = A1; lda = lda1; kcol = k0; }
        else             { A = A2; lda = lda2; kcol = k0 - Ksplit; }

        #pragma unroll
        for (int r = 0; r < 8; r++) {
            int m = rrow + r * 8;
            As[kk][m] = A[(size_t)(mBase + m) * lda + kcol + kk];
        }
        #pragma unroll
        for (int r = 0; r < 8; r++) {
            int n = rrow + r * 8;
            float v = 0.f;
            if (nBase + n < Nn) v = W[(size_t)(nBase + n) * K + k0 + kk];
            Bs[kk][n] = v;
        }
        __syncthreads();

        #pragma unroll
        for (int q = 0; q < BKC; q++) {
            float4 av = *(const float4*)&As[q][tx * 4];
            float4 bv = *(const float4*)&Bs[q][ty * 4];
            float am[4] = {av.x, av.y, av.z, av.w};
            float bn[4] = {bv.x, bv.y, bv.z, bv.w};
            #pragma unroll
            for (int i = 0; i < 4; i++)
                #pragma unroll
                for (int j = 0; j < 4; j++)
                    acc[i][j] = fmaf(am[i], bn[j], acc[i][j]);
        }
        __syncthreads();
    }

    #pragma unroll
    for (int i = 0; i < 4; i++) {
        int row = mBase + tx * 4 + i;
        #pragma unroll
        for (int j = 0; j < 4; j++) {
            int col = nBase + ty * 4 + j;
            if (col < Nn)
                Cout[(size_t)row * Nn + col] = acc[i][j] + bias[col];
        }
    }
}

// ---------------------------------------------------------------------------
// Window attention. Grid (BATCH, NHEADS, 2). 128 threads.
//   z = 0: source = Ys  -> typeA = attn_cv (scale),  typeB = attn_sh (scale^2)
//   z = 1: source = Ye  -> typeA = attn_sv (1.0),    typeB = attn_ch (scale)
// Tiles j4 = 0(k), 1(v), 2(qA), 3(qB) -- identical role for both z.
// 4 warps: warps {0,1} = type A (query-row halves), {2,3} = type B.
// Dynamic smem: 4 q/k/v tiles [64][33] + scores S[2][64][65] = 67072 B.
// ---------------------------------------------------------------------------
#define TPITCH 33
#define TSIZE  (NTOK * TPITCH)     // 2112 floats per tile
#define SPITCH 65
#define ATTN_SMEM ((4 * TSIZE + 2 * NTOK * SPITCH) * sizeof(float))

__global__ __launch_bounds__(128)
void attn_kernel(const float* __restrict__ tcv, const float* __restrict__ tsv,
                 const float* __restrict__ tch, const float* __restrict__ tsh,
                 const int*   __restrict__ rel_idx)
{
    extern __shared__ float smem[];
    float* tiles = smem;                      // 4 * 2112
    float* S     = smem + 4 * TSIZE;          // 2 * 64 * 65

    const int b = blockIdx.x;
    const int h = blockIdx.y;
    const int z = blockIdx.z;

    const float* Y = z ? g_Ye : g_Ys;
    const float* tblA = z ? tsv : tcv;
    const float* tblB = z ? tch : tsh;
    const float  sclA = z ? 1.0f  : SCALE;
    const float  sclB = z ? SCALE : SCALE * SCALE;
    float* outA = z ? g_Msv : g_Mcv;
    float* outB = z ? g_Mch : g_Msh;

    const int t    = threadIdx.x;
    const int lane = t & 31;
    const int warp = t >> 5;

    // ---- load 4 projection tiles [64][32] (cols j4*96 + h*32 + lane) ----
    #pragma unroll
    for (int j4 = 0; j4 < 4; j4++) {
        #pragma unroll
        for (int r = 0; r < 16; r++) {
            int i = warp * 16 + r;
            tiles[j4 * TSIZE + i * TPITCH + lane] =
                Y[(size_t)(b * NTOK + i) * K4 + j4 * CDIM + h * HD + lane];
        }
    }

    // ---- pre-fill scores with relative-position bias ----
    for (int idx = t; idx < NTOK * NTOK; idx += 128) {
        int r = rel_idx[idx];
        int i = idx >> 6, j = idx & 63;
        float ba = tblA[r * NHEADS + h];
        float bb = tblB[r * NHEADS + h];
        S[i * SPITCH + j]                  = ba;
        S[(NTOK + i) * SPITCH + j]         = bb;
    }
    __syncthreads();

    const int type = warp >> 1;     // 0 = A, 1 = B
    const int half = warp & 1;      // query-row half
    const float* q = tiles + (2 + type) * TSIZE;
    const float* k = tiles;                 // j4 = 0
    const float* v = tiles + TSIZE;         // j4 = 1
    const float  scl = type ? sclB : sclA;
    float* St = S + type * NTOK * SPITCH;
    float* outP = type ? outB : outA;

    // ---- Q @ K^T (lane owns columns j0=lane, j1=lane+32; 4-row blocking) ----
    const int j0 = lane, j1 = lane + 32;
    for (int i0 = half * 32; i0 < half * 32 + 32; i0 += 4) {
        float a0[4], a1[4];
        #pragma unroll
        for (int r = 0; r < 4; r++) { a0[r] = 0.f; a1[r] = 0.f; }
        #pragma unroll
        for (int d = 0; d < HD; d++) {
            float k0v = k[j0 * TPITCH + d];
            float k1v = k[j1 * TPITCH + d];
            #pragma unroll
            for (int r = 0; r < 4; r++) {
                float qv = q[(i0 + r) * TPITCH + d];
                a0[r] = fmaf(qv, k0v, a0[r]);
                a1[r] = fmaf(qv, k1v, a1[r]);
            }
        }
        #pragma unroll
        for (int r = 0; r < 4; r++) {
            St[(i0 + r) * SPITCH + j0] = fmaf(scl, a0[r], St[(i0 + r) * SPITCH + j0]);
            St[(i0 + r) * SPITCH + j1] = fmaf(scl, a1[r], St[(i0 + r) * SPITCH + j1]);
        }
    }
    __syncwarp();

    // ---- row softmax (each lane owns one row of its half) ----
    {
        int row = half * 32 + lane;
        float* Sr = St + row * SPITCH;
        float mx = -1e30f;
        #pragma unroll
        for (int j = 0; j < NTOK; j++) mx = fmaxf(mx, Sr[j]);
        float sum = 0.f;
        #pragma unroll
        for (int j = 0; j < NTOK; j++) {
            float e = __expf(Sr[j] - mx);
            Sr[j] = e;
            sum += e;
        }
        float inv = 1.f / sum;
        #pragma unroll
        for (int j = 0; j < NTOK; j++) Sr[j] *= inv;
    }
    __syncwarp();

    // ---- P @ V (lane owns output dim d=lane; 4-row blocking) ----
    for (int i0 = half * 32; i0 < half * 32 + 32; i0 += 4) {
        float acc[4] = {0.f, 0.f, 0.f, 0.f};
        #pragma unroll 8
        for (int j = 0; j < NTOK; j++) {
            float vv = v[j * TPITCH + lane];
            #pragma unroll
            for (int r = 0; r < 4; r++)
                acc[r] = fmaf(St[(i0 + r) * SPITCH + j], vv, acc[r]);
        }
        #pragma unroll
        for (int r = 0; r < 4; r++)
            outP[(size_t)(b * NTOK + i0 + r) * CDIM + h * HD + lane] = acc[r];
    }
}

// ---------------------------------------------------------------------------
// Launch
// ---------------------------------------------------------------------------
extern "C" void kernel_launch(void* const* d_in, const int* in_sizes, int n_in,
                              void* d_out, int out_size)
{
    const float* input_x = (const float*)d_in[0];
    const float* state_x = (const float*)d_in[1];
    const float* Ws      = (const float*)d_in[2];
    const float* bs      = (const float*)d_in[3];
    const float* We      = (const float*)d_in[4];
    const float* be      = (const float*)d_in[5];
    const float* tcv     = (const float*)d_in[6];
    const float* tsv     = (const float*)d_in[7];
    const float* tch     = (const float*)d_in[8];
    const float* tsh     = (const float*)d_in[9];
    const float* Wpv     = (const float*)d_in[10];
    const float* bpv     = (const float*)d_in[11];
    const float* Wph     = (const float*)d_in[12];
    const float* bph     = (const float*)d_in[13];
    const int*   rel_idx = (const int*)d_in[14];

    float* out   = (float*)d_out;
    float* state = out + (size_t)BATCH * NTOK * CDIM;

    float *pYs, *pYe, *pMcv, *pMsv, *pMch, *pMsh;
    cudaGetSymbolAddress((void**)&pYs,  g_Ys);
    cudaGetSymbolAddress((void**)&pYe,  g_Ye);
    cudaGetSymbolAddress((void**)&pMcv, g_Mcv);
    cudaGetSymbolAddress((void**)&pMsv, g_Msv);
    cudaGetSymbolAddress((void**)&pMch, g_Mch);
    cudaGetSymbolAddress((void**)&pMsh, g_Msh);

    cudaFuncSetAttribute(attn_kernel,
                         cudaFuncAttributeMaxDynamicSharedMemorySize,
                         (int)ATTN_SMEM);

    const int M = BATCH * NTOK;          // 262144

    // Stage 1: projections  Y = X @ W^T + b   -> [M, 384]
    {
        dim3 grid(M / BM, K4 / BN);
        gemm_bias<<<grid, 256>>>(state_x, state_x, CDIM, CDIM, CDIM, CDIM, K4,
                                 Ws, bs, pYs);
        gemm_bias<<<grid, 256>>>(input_x, input_x, CDIM, CDIM, CDIM, CDIM, K4,
                                 We, be, pYe);
    }

    // Stage 2: 4 window attentions per (b, h)
    {
        dim3 grid(BATCH, NHEADS, 2);
        attn_kernel<<<grid, 128, ATTN_SMEM>>>(tcv, tsv, tch, tsh, rel_idx);
    }

    // Stage 3: output projections on concatenated merges
    {
        dim3 grid(M / BM, (CDIM + BN - 1) / BN);   // (4096, 2)
        gemm_bias<<<grid, 256>>>(pMcv, pMsv, CDIM, CDIM, CDIM, 2 * CDIM, CDIM,
                                 Wpv, bpv, out);
        gemm_bias<<<grid, 256>>>(pMch, pMsh, CDIM, CDIM, CDIM, 2 * CDIM, CDIM,
                                 Wph, bph, state);
    }
}